// round 16
// baseline (speedup 1.0000x reference)
#include <cuda_runtime.h>
#include <cuda_bf16.h>
#include <cstdint>

#define Nn 50000
#define Ee 800000
#define INF 256
#define OUTF 128
#define NEG_SLOPE 0.2f
#define ALPHA 0.5f

#define SCAN_T 256
#define SCAN_BLOCKS ((Nn + SCAN_T - 1) / SCAN_T)   // 196
#define BSPLIT_BLOCKS ((INF * OUTF) / 256)         // 128
#define DEG_BLOCKS ((Ee + 255) / 256)              // 3125

// Scratch (static device globals; no runtime allocation)
__device__ float  g_ft[(size_t)Nn * OUTF];   // fc projection [N,128]
__device__ float  g_el[Nn];
__device__ float  g_er[Nn];
__device__ int    g_deg[Nn];                 // in-degree (zeroed by scan_a after use)
__device__ int    g_off[Nn + 1];             // CSR offsets
__device__ int    g_blk[SCAN_BLOCKS];        // per-block degree totals
__device__ int    g_pos[Ee];                 // within-bucket rank of each edge
__device__ float4 g_sz[Ee];                  // (src bits, exp(e), exp(w), -) bucketed by dst
// bf16 split of fc_w, transposed to [n][k]
__device__ __nv_bfloat16 g_bhi[OUTF * INF];
__device__ __nv_bfloat16 g_blo[OUTF * INF];

__device__ __forceinline__ uint32_t smem_u32(const void* p) {
    uint32_t a;
    asm("{ .reg .u64 t; cvta.to.shared.u64 t, %1; cvt.u32.u64 %0, t; }"
        : "=r"(a) : "l"(p));
    return a;
}

#define LDMATRIX_X4(q0, q1, q2, q3, addr) \
    asm volatile("ldmatrix.sync.aligned.m8n8.x4.shared.b16 {%0,%1,%2,%3}, [%4];" \
                 : "=r"(q0), "=r"(q1), "=r"(q2), "=r"(q3) : "r"(addr))

#define MMA16816(d, a0, a1, a2, a3, b0, b1) \
    asm volatile("mma.sync.aligned.m16n8k16.row.col.f32.bf16.bf16.f32 " \
                 "{%0,%1,%2,%3}, {%4,%5,%6,%7}, {%8,%9}, {%0,%1,%2,%3};" \
                 : "+f"((d)[0]), "+f"((d)[1]), "+f"((d)[2]), "+f"((d)[3]) \
                 : "r"(a0), "r"(a1), "r"(a2), "r"(a3), "r"(b0), "r"(b1))

#define CP_ASYNC16(dst, src) \
    asm volatile("cp.async.cg.shared.global [%0], [%1], 16;" :: "r"(dst), "l"(src))
#define CP_ASYNC_WAIT_ALL() asm volatile("cp.async.wait_all;" ::: "memory")

// ---------------------------------------------------------------------------
// Fused prologue: blocks [0,128) transpose+split fc_w; blocks [128, ...) do
// the degree histogram AND record each edge's within-bucket rank.
// ---------------------------------------------------------------------------
__global__ void k_pre(const float* __restrict__ fcw, const int* __restrict__ dst) {
    int b = blockIdx.x;
    if (b < BSPLIT_BLOCKS) {
        int idx = b * 256 + threadIdx.x;     // < 32768 always
        int k = idx >> 7, n = idx & 127;
        float v = fcw[idx];
        __nv_bfloat16 h = __float2bfloat16(v);
        __nv_bfloat16 l = __float2bfloat16(v - __bfloat162float(h));
        g_bhi[n * INF + k] = h;
        g_blo[n * INF + k] = l;
    } else {
        int i = (b - BSPLIT_BLOCKS) * 256 + threadIdx.x;
        if (i < Ee) g_pos[i] = atomicAdd(&g_deg[dst[i]], 1);
    }
}

// ---------------------------------------------------------------------------
// Tensor-core GEMM (mma.sync bf16, 3-term split): g_ft = feat @ fc_w, fp32 acc.
// Block: 256 threads = 8 warps as 4(M) x 2(N); warp tile m32 x n64.
// R8-VALIDATED (50.6us): single-stage static smem, A reg-prefetch, B cp.async.
// Fused epilogue: g_ft store + el/er dot products (smem-combined, no atomics).
// ---------------------------------------------------------------------------
#define STR 40   // smem row stride in bf16 (32 data + 8 pad -> conflict-free ldmatrix)

__global__ __launch_bounds__(256) void k_gemm(const float* __restrict__ feat,
                                              const float* __restrict__ attn_l,
                                              const float* __restrict__ attn_r) {
    __shared__ __nv_bfloat16 sAhi[128 * STR];
    __shared__ __nv_bfloat16 sAlo[128 * STR];
    __shared__ __nv_bfloat16 sBhi[128 * STR];
    __shared__ __nv_bfloat16 sBlo[128 * STR];

    int tid = threadIdx.x;
    int warp = tid >> 5, lane = tid & 31;
    int mw = warp & 3;        // M-warp: rows mw*32 .. +32
    int nw = warp >> 2;       // N-warp: cols nw*64 .. +64
    int row0 = blockIdx.x * 128;

    float acc[2][8][4];       // [mtile][n8tile][frag]
#pragma unroll
    for (int i = 0; i < 2; i++)
#pragma unroll
        for (int j = 0; j < 8; j++)
#pragma unroll
            for (int q = 0; q < 4; q++) acc[i][j][q] = 0.f;

    // per-thread load coords: thread t -> row t/2, 16-col half (t&1)
    int lr = tid >> 1;
    int lc = (tid & 1) * 16;
    bool a_valid = (row0 + lr) < Nn;
    const float4* a_src = (const float4*)(feat + (size_t)(row0 + lr) * INF + lc);

    uint32_t uAhi = smem_u32(sAhi), uAlo = smem_u32(sAlo);
    uint32_t uBhi = smem_u32(sBhi), uBlo = smem_u32(sBlo);

    // ldmatrix lane addressing: row = base + (lane&15), col = k0 + (lane>>4)*8
    int lm_r = lane & 15;
    int lm_c = (lane >> 4) * 8;

    // prefetch chunk 0 of A into registers
    float4 va[4];
#pragma unroll
    for (int i = 0; i < 4; i++)
        va[i] = a_valid ? a_src[i] : make_float4(0.f, 0.f, 0.f, 0.f);

    for (int kc = 0; kc < 8; kc++) {
        int kk = kc * 32;
        __syncthreads();   // previous chunk's ldsm reads complete

        // ---- B chunk via cp.async (bf16, no conversion) ----
        {
            const char* gh = (const char*)(g_bhi + (size_t)lr * INF + kk + lc);
            const char* gl = (const char*)(g_blo + (size_t)lr * INF + kk + lc);
            uint32_t dh = uBhi + (uint32_t)(lr * STR + lc) * 2;
            uint32_t dl = uBlo + (uint32_t)(lr * STR + lc) * 2;
            CP_ASYNC16(dh, gh);
            CP_ASYNC16(dh + 16, gh + 16);
            CP_ASYNC16(dl, gl);
            CP_ASYNC16(dl + 16, gl + 16);
        }

        // ---- A split from prefetched regs -> smem ----
        {
            __nv_bfloat162* dh = (__nv_bfloat162*)&sAhi[lr * STR + lc];
            __nv_bfloat162* dl = (__nv_bfloat162*)&sAlo[lr * STR + lc];
#pragma unroll
            for (int i = 0; i < 4; i++) {
                float4 v = va[i];
                __nv_bfloat16 h0 = __float2bfloat16(v.x), h1 = __float2bfloat16(v.y);
                __nv_bfloat16 h2 = __float2bfloat16(v.z), h3 = __float2bfloat16(v.w);
                dh[i * 2 + 0] = __nv_bfloat162(h0, h1);
                dh[i * 2 + 1] = __nv_bfloat162(h2, h3);
                dl[i * 2 + 0] = __nv_bfloat162(
                    __float2bfloat16(v.x - __bfloat162float(h0)),
                    __float2bfloat16(v.y - __bfloat162float(h1)));
                dl[i * 2 + 1] = __nv_bfloat162(
                    __float2bfloat16(v.z - __bfloat162float(h2)),
                    __float2bfloat16(v.w - __bfloat162float(h3)));
            }
        }

        // ---- prefetch next A chunk (overlaps with MMAs below) ----
        if (kc < 7) {
            const float4* nxt = a_src + (kk + 32) / 4;
#pragma unroll
            for (int i = 0; i < 4; i++)
                va[i] = a_valid ? nxt[i] : make_float4(0.f, 0.f, 0.f, 0.f);
        }

        CP_ASYNC_WAIT_ALL();
        __syncthreads();

        // ---- MMA: 2 k16-steps per chunk ----
#pragma unroll
        for (int ks = 0; ks < 2; ks++) {
            int k0 = ks * 16;
            uint32_t ah[2][4], al[2][4];
#pragma unroll
            for (int mt = 0; mt < 2; mt++) {
                uint32_t aoff = (uint32_t)(((mw * 32 + mt * 16 + lm_r) * STR + k0 + lm_c) * 2);
                LDMATRIX_X4(ah[mt][0], ah[mt][1], ah[mt][2], ah[mt][3], uAhi + aoff);
                LDMATRIX_X4(al[mt][0], al[mt][1], al[mt][2], al[mt][3], uAlo + aoff);
            }
#pragma unroll
            for (int g = 0; g < 4; g++) {       // n16 tiles within warp's n64
                uint32_t boff = (uint32_t)(((nw * 64 + g * 16 + lm_r) * STR + k0 + lm_c) * 2);
                uint32_t q0, q1, q2, q3;
                LDMATRIX_X4(q0, q1, q2, q3, uBhi + boff);
#pragma unroll
                for (int mt = 0; mt < 2; mt++) {
                    MMA16816(acc[mt][2 * g],     ah[mt][0], ah[mt][1], ah[mt][2], ah[mt][3], q0, q2);
                    MMA16816(acc[mt][2 * g + 1], ah[mt][0], ah[mt][1], ah[mt][2], ah[mt][3], q1, q3);
                    MMA16816(acc[mt][2 * g],     al[mt][0], al[mt][1], al[mt][2], al[mt][3], q0, q2);
                    MMA16816(acc[mt][2 * g + 1], al[mt][0], al[mt][1], al[mt][2], al[mt][3], q1, q3);
                }
                LDMATRIX_X4(q0, q1, q2, q3, uBlo + boff);
#pragma unroll
                for (int mt = 0; mt < 2; mt++) {
                    MMA16816(acc[mt][2 * g],     ah[mt][0], ah[mt][1], ah[mt][2], ah[mt][3], q0, q2);
                    MMA16816(acc[mt][2 * g + 1], ah[mt][0], ah[mt][1], ah[mt][2], ah[mt][3], q1, q3);
                }
            }
        }
    }

    // ---- epilogue: store g_ft + fused el/er (no atomics) ----
    __syncthreads();                    // all MMAs done; smem reusable
    float4* scr = (float4*)sAhi;        // 64 float4 scratch
    float p[2][4];
#pragma unroll
    for (int mt = 0; mt < 2; mt++) {
        int r1 = row0 + mw * 32 + mt * 16 + (lane >> 2);
        int r2 = r1 + 8;
        float pl1 = 0.f, pr1 = 0.f, pl2 = 0.f, pr2 = 0.f;
#pragma unroll
        for (int nt = 0; nt < 8; nt++) {
            int c = nw * 64 + nt * 8 + (lane & 3) * 2;
            float wl0 = attn_l[c], wl1 = attn_l[c + 1];
            float wr0 = attn_r[c], wr1 = attn_r[c + 1];
            pl1 += acc[mt][nt][0] * wl0 + acc[mt][nt][1] * wl1;
            pr1 += acc[mt][nt][0] * wr0 + acc[mt][nt][1] * wr1;
            pl2 += acc[mt][nt][2] * wl0 + acc[mt][nt][3] * wl1;
            pr2 += acc[mt][nt][2] * wr0 + acc[mt][nt][3] * wr1;
            if (r1 < Nn)
                *(float2*)(g_ft + (size_t)r1 * OUTF + c) = make_float2(acc[mt][nt][0], acc[mt][nt][1]);
            if (r2 < Nn)
                *(float2*)(g_ft + (size_t)r2 * OUTF + c) = make_float2(acc[mt][nt][2], acc[mt][nt][3]);
        }
#pragma unroll
        for (int o = 1; o <= 2; o <<= 1) {
            pl1 += __shfl_xor_sync(0xFFFFFFFFu, pl1, o);
            pr1 += __shfl_xor_sync(0xFFFFFFFFu, pr1, o);
            pl2 += __shfl_xor_sync(0xFFFFFFFFu, pl2, o);
            pr2 += __shfl_xor_sync(0xFFFFFFFFu, pr2, o);
        }
        p[mt][0] = pl1; p[mt][1] = pr1; p[mt][2] = pl2; p[mt][3] = pr2;
        if (nw == 0 && (lane & 3) == 0)
            scr[(mw * 2 + mt) * 8 + (lane >> 2)] = make_float4(pl1, pr1, pl2, pr2);
    }
    __syncthreads();
    if (nw == 1 && (lane & 3) == 0) {
#pragma unroll
        for (int mt = 0; mt < 2; mt++) {
            float4 q = scr[(mw * 2 + mt) * 8 + (lane >> 2)];
            int r1 = row0 + mw * 32 + mt * 16 + (lane >> 2);
            int r2 = r1 + 8;
            if (r1 < Nn) { g_el[r1] = q.x + p[mt][0]; g_er[r1] = q.y + p[mt][1]; }
            if (r2 < Nn) { g_el[r2] = q.z + p[mt][2]; g_er[r2] = q.w + p[mt][3]; }
        }
    }
}

// ---------------------------------------------------------------------------
// Scan phase A: warp-shuffle scan over degrees (2 barriers); zeroes g_deg.
// ---------------------------------------------------------------------------
__global__ __launch_bounds__(SCAN_T) void k_scan_a() {
    __shared__ int ws[8];
    int t = threadIdx.x;
    int lane = t & 31, wp = t >> 5;
    int i = blockIdx.x * SCAN_T + t;
    int d = (i < Nn) ? g_deg[i] : 0;
    if (i < Nn) g_deg[i] = 0;          // self-reset for next replay

    int v = d;                          // warp-inclusive scan
#pragma unroll
    for (int o = 1; o < 32; o <<= 1) {
        int n = __shfl_up_sync(0xFFFFFFFFu, v, o);
        if (lane >= o) v += n;
    }
    if (lane == 31) ws[wp] = v;
    __syncthreads();
    if (t < 8) {
        int s = ws[t];
#pragma unroll
        for (int o = 1; o < 8; o <<= 1) {
            int n = __shfl_up_sync(0xFFu, s, o);
            if (t >= o) s += n;
        }
        ws[t] = s;                      // inclusive warp-sum prefix
    }
    __syncthreads();
    int wpref = wp ? ws[wp - 1] : 0;
    if (i < Nn) g_off[i] = wpref + v - d;           // exclusive within block
    if (t == SCAN_T - 1) g_blk[blockIdx.x] = ws[7]; // block total
}

// ---------------------------------------------------------------------------
// Scan phase C (fused B): warp-shuffle reduce g_blk[0..b), add prefix.
// ---------------------------------------------------------------------------
__global__ __launch_bounds__(SCAN_T) void k_scan_c() {
    __shared__ int ws[8];
    __shared__ int spref;
    int t = threadIdx.x;
    int lane = t & 31, wp = t >> 5;
    int b = blockIdx.x;

    int x = (t < b && t < SCAN_BLOCKS) ? g_blk[t] : 0;
#pragma unroll
    for (int o = 16; o; o >>= 1) x += __shfl_xor_sync(0xFFFFFFFFu, x, o);
    if (lane == 0) ws[wp] = x;
    __syncthreads();
    if (t == 0) {
        int s = 0;
#pragma unroll
        for (int j = 0; j < 8; j++) s += ws[j];
        spref = s;
    }
    __syncthreads();

    int i = b * SCAN_T + t;
    if (i < Nn) g_off[i] += spref;
    if (i == 0) g_off[Nn] = Ee;
}

// ---------------------------------------------------------------------------
// Scatter: NO atomics — pos = off[dst] + precomputed rank. One float4 store.
// ---------------------------------------------------------------------------
__global__ void k_scatter(const float* __restrict__ w,
                          const int* __restrict__ src, const int* __restrict__ dst) {
    int i = blockIdx.x * blockDim.x + threadIdx.x;
    if (i >= Ee) return;
    int s = src[i], d = dst[i];
    float e = g_el[s] + g_er[d];
    e = e > 0.f ? e : NEG_SLOPE * e;
    float z  = expf(e);
    float zw = expf(w[i]);
    int pos = g_off[d] + g_pos[i];
    g_sz[pos] = make_float4(__int_as_float(s), z, zw, 0.f);
}

// ---------------------------------------------------------------------------
// CSR aggregation: one warp per dst node, no atomics. Pass 1 warp-reduces
// se/sw; pass 2 gathers ft[src] with 4-deep LDG pipelining (MLP=4).
// ---------------------------------------------------------------------------
__global__ __launch_bounds__(256) void k_agg_csr(const float* __restrict__ bias,
                                                 float* __restrict__ out) {
    int node = blockIdx.x * 8 + (threadIdx.x >> 5);
    int lane = threadIdx.x & 31;
    if (node >= Nn) return;
    int beg = g_off[node], end = g_off[node + 1];

    // pass 1: segment sums
    float se = 0.f, sw = 0.f;
    for (int i = beg + lane; i < end; i += 32) {
        float4 t = g_sz[i];
        se += t.y;
        sw += t.z;
    }
#pragma unroll
    for (int o = 16; o; o >>= 1) {
        se += __shfl_xor_sync(0xFFFFFFFFu, se, o);
        sw += __shfl_xor_sync(0xFFFFFFFFu, sw, o);
    }
    float inv_se = __fdividef(1.f - ALPHA, se);
    float inv_sw = __fdividef(ALPHA, sw);

    float4 acc = *(const float4*)(bias + lane * 4);
    const float* ftl = g_ft + lane * 4;

    for (int base = beg; base < end; base += 32) {
        int n = min(32, end - base);
        int s = 0;
        float a = 0.f;
        if (lane < n) {
            float4 t = g_sz[base + lane];
            s = __float_as_int(t.x);
            a = t.y * inv_se + t.z * inv_sw;
        }
        int j = 0;
        for (; j + 4 <= n; j += 4) {
            int   s0 = __shfl_sync(0xFFFFFFFFu, s, j);
            int   s1 = __shfl_sync(0xFFFFFFFFu, s, j + 1);
            int   s2 = __shfl_sync(0xFFFFFFFFu, s, j + 2);
            int   s3 = __shfl_sync(0xFFFFFFFFu, s, j + 3);
            float a0 = __shfl_sync(0xFFFFFFFFu, a, j);
            float a1 = __shfl_sync(0xFFFFFFFFu, a, j + 1);
            float a2 = __shfl_sync(0xFFFFFFFFu, a, j + 2);
            float a3 = __shfl_sync(0xFFFFFFFFu, a, j + 3);
            float4 v0 = *(const float4*)(ftl + (size_t)s0 * OUTF);
            float4 v1 = *(const float4*)(ftl + (size_t)s1 * OUTF);
            float4 v2 = *(const float4*)(ftl + (size_t)s2 * OUTF);
            float4 v3 = *(const float4*)(ftl + (size_t)s3 * OUTF);
            acc.x = fmaf(a0, v0.x, acc.x); acc.y = fmaf(a0, v0.y, acc.y);
            acc.z = fmaf(a0, v0.z, acc.z); acc.w = fmaf(a0, v0.w, acc.w);
            acc.x = fmaf(a1, v1.x, acc.x); acc.y = fmaf(a1, v1.y, acc.y);
            acc.z = fmaf(a1, v1.z, acc.z); acc.w = fmaf(a1, v1.w, acc.w);
            acc.x = fmaf(a2, v2.x, acc.x); acc.y = fmaf(a2, v2.y, acc.y);
            acc.z = fmaf(a2, v2.z, acc.z); acc.w = fmaf(a2, v2.w, acc.w);
            acc.x = fmaf(a3, v3.x, acc.x); acc.y = fmaf(a3, v3.y, acc.y);
            acc.z = fmaf(a3, v3.z, acc.z); acc.w = fmaf(a3, v3.w, acc.w);
        }
        for (; j < n; j++) {
            int   sj = __shfl_sync(0xFFFFFFFFu, s, j);
            float aj = __shfl_sync(0xFFFFFFFFu, a, j);
            float4 v = *(const float4*)(ftl + (size_t)sj * OUTF);
            acc.x = fmaf(aj, v.x, acc.x);
            acc.y = fmaf(aj, v.y, acc.y);
            acc.z = fmaf(aj, v.z, acc.z);
            acc.w = fmaf(aj, v.w, acc.w);
        }
    }
    *(float4*)(out + (size_t)node * OUTF + lane * 4) = acc;
}

extern "C" void kernel_launch(void* const* d_in, const int* in_sizes, int n_in,
                              void* d_out, int out_size) {
    const float* feat   = (const float*)d_in[0];
    const float* w      = (const float*)d_in[1];
    const float* fcw    = (const float*)d_in[2];
    const float* attn_l = (const float*)d_in[3];
    const float* attn_r = (const float*)d_in[4];
    const float* bias   = (const float*)d_in[5];
    const int*   src    = (const int*)d_in[6];
    const int*   dst    = (const int*)d_in[7];
    float* out = (float*)d_out;

    k_pre<<<BSPLIT_BLOCKS + DEG_BLOCKS, 256>>>(fcw, dst);
    k_scan_a<<<SCAN_BLOCKS, SCAN_T>>>();
    k_scan_c<<<SCAN_BLOCKS, SCAN_T>>>();
    k_gemm<<<(Nn + 127) / 128, 256>>>(feat, attn_l, attn_r);   // 4th: profiled
    k_scatter<<<(Ee + 255) / 256, 256>>>(w, src, dst);
    k_agg_csr<<<(Nn + 7) / 8, 256>>>(bias, out);
}

// round 17
// speedup vs baseline: 1.0142x; 1.0142x over previous
#include <cuda_runtime.h>
#include <cuda_bf16.h>
#include <cstdint>

#define Nn 50000
#define Ee 800000
#define INF 256
#define OUTF 128
#define NEG_SLOPE 0.2f
#define ALPHA 0.5f

#define SCAN_T 256
#define SCAN_BLOCKS ((Nn + SCAN_T - 1) / SCAN_T)   // 196
#define BSPLIT_BLOCKS ((INF * OUTF) / 256)         // 128
#define DEG_BLOCKS ((Ee + 255) / 256)              // 3125

// Scratch (static device globals; no runtime allocation)
__device__ float  g_ft[(size_t)Nn * OUTF];   // fc projection [N,128]
__device__ float  g_el[Nn];
__device__ float  g_er[Nn];
__device__ int    g_deg[Nn];                 // in-degree (zeroed by scan_a after use)
__device__ int    g_off[Nn + 1];             // CSR offsets
__device__ int    g_blk[SCAN_BLOCKS];        // per-block degree totals
__device__ int    g_pos[Ee];                 // within-bucket rank of each edge
__device__ float4 g_sz[Ee];                  // (src bits, exp(e), exp(w), -) bucketed by dst
// bf16 split of fc_w, transposed to [n][k]
__device__ __nv_bfloat16 g_bhi[OUTF * INF];
__device__ __nv_bfloat16 g_blo[OUTF * INF];

__device__ __forceinline__ uint32_t smem_u32(const void* p) {
    uint32_t a;
    asm("{ .reg .u64 t; cvta.to.shared.u64 t, %1; cvt.u32.u64 %0, t; }"
        : "=r"(a) : "l"(p));
    return a;
}

#define LDMATRIX_X4(q0, q1, q2, q3, addr) \
    asm volatile("ldmatrix.sync.aligned.m8n8.x4.shared.b16 {%0,%1,%2,%3}, [%4];" \
                 : "=r"(q0), "=r"(q1), "=r"(q2), "=r"(q3) : "r"(addr))

#define MMA16816(d, a0, a1, a2, a3, b0, b1) \
    asm volatile("mma.sync.aligned.m16n8k16.row.col.f32.bf16.bf16.f32 " \
                 "{%0,%1,%2,%3}, {%4,%5,%6,%7}, {%8,%9}, {%0,%1,%2,%3};" \
                 : "+f"((d)[0]), "+f"((d)[1]), "+f"((d)[2]), "+f"((d)[3]) \
                 : "r"(a0), "r"(a1), "r"(a2), "r"(a3), "r"(b0), "r"(b1))

#define CP_ASYNC16(dst, src) \
    asm volatile("cp.async.cg.shared.global [%0], [%1], 16;" :: "r"(dst), "l"(src))
#define CP_ASYNC_WAIT_ALL() asm volatile("cp.async.wait_all;" ::: "memory")

// ---------------------------------------------------------------------------
// Fused prologue: blocks [0,128) transpose+split fc_w; blocks [128, ...) do
// the degree histogram AND record each edge's within-bucket rank.
// ---------------------------------------------------------------------------
__global__ void k_pre(const float* __restrict__ fcw, const int* __restrict__ dst) {
    int b = blockIdx.x;
    if (b < BSPLIT_BLOCKS) {
        int idx = b * 256 + threadIdx.x;     // < 32768 always
        int k = idx >> 7, n = idx & 127;
        float v = fcw[idx];
        __nv_bfloat16 h = __float2bfloat16(v);
        __nv_bfloat16 l = __float2bfloat16(v - __bfloat162float(h));
        g_bhi[n * INF + k] = h;
        g_blo[n * INF + k] = l;
    } else {
        int i = (b - BSPLIT_BLOCKS) * 256 + threadIdx.x;
        if (i < Ee) g_pos[i] = atomicAdd(&g_deg[dst[i]], 1);
    }
}

// ---------------------------------------------------------------------------
// Tensor-core GEMM (mma.sync bf16, 3-term split): g_ft = feat @ fc_w, fp32 acc.
// Block: 256 threads = 8 warps as 4(M) x 2(N); warp tile m32 x n64.
// R8-VALIDATED (50.6us): single-stage static smem, A reg-prefetch, B cp.async.
// Fused epilogue: g_ft store + el/er dot products (smem-combined, no atomics).
// ---------------------------------------------------------------------------
#define STR 40   // smem row stride in bf16 (32 data + 8 pad -> conflict-free ldmatrix)

__global__ __launch_bounds__(256) void k_gemm(const float* __restrict__ feat,
                                              const float* __restrict__ attn_l,
                                              const float* __restrict__ attn_r) {
    __shared__ __nv_bfloat16 sAhi[128 * STR];
    __shared__ __nv_bfloat16 sAlo[128 * STR];
    __shared__ __nv_bfloat16 sBhi[128 * STR];
    __shared__ __nv_bfloat16 sBlo[128 * STR];

    int tid = threadIdx.x;
    int warp = tid >> 5, lane = tid & 31;
    int mw = warp & 3;        // M-warp: rows mw*32 .. +32
    int nw = warp >> 2;       // N-warp: cols nw*64 .. +64
    int row0 = blockIdx.x * 128;

    float acc[2][8][4];       // [mtile][n8tile][frag]
#pragma unroll
    for (int i = 0; i < 2; i++)
#pragma unroll
        for (int j = 0; j < 8; j++)
#pragma unroll
            for (int q = 0; q < 4; q++) acc[i][j][q] = 0.f;

    // per-thread load coords: thread t -> row t/2, 16-col half (t&1)
    int lr = tid >> 1;
    int lc = (tid & 1) * 16;
    bool a_valid = (row0 + lr) < Nn;
    const float4* a_src = (const float4*)(feat + (size_t)(row0 + lr) * INF + lc);

    uint32_t uAhi = smem_u32(sAhi), uAlo = smem_u32(sAlo);
    uint32_t uBhi = smem_u32(sBhi), uBlo = smem_u32(sBlo);

    // ldmatrix lane addressing: row = base + (lane&15), col = k0 + (lane>>4)*8
    int lm_r = lane & 15;
    int lm_c = (lane >> 4) * 8;

    // prefetch chunk 0 of A into registers
    float4 va[4];
#pragma unroll
    for (int i = 0; i < 4; i++)
        va[i] = a_valid ? a_src[i] : make_float4(0.f, 0.f, 0.f, 0.f);

    for (int kc = 0; kc < 8; kc++) {
        int kk = kc * 32;
        __syncthreads();   // previous chunk's ldsm reads complete

        // ---- B chunk via cp.async (bf16, no conversion) ----
        {
            const char* gh = (const char*)(g_bhi + (size_t)lr * INF + kk + lc);
            const char* gl = (const char*)(g_blo + (size_t)lr * INF + kk + lc);
            uint32_t dh = uBhi + (uint32_t)(lr * STR + lc) * 2;
            uint32_t dl = uBlo + (uint32_t)(lr * STR + lc) * 2;
            CP_ASYNC16(dh, gh);
            CP_ASYNC16(dh + 16, gh + 16);
            CP_ASYNC16(dl, gl);
            CP_ASYNC16(dl + 16, gl + 16);
        }

        // ---- A split from prefetched regs -> smem ----
        {
            __nv_bfloat162* dh = (__nv_bfloat162*)&sAhi[lr * STR + lc];
            __nv_bfloat162* dl = (__nv_bfloat162*)&sAlo[lr * STR + lc];
#pragma unroll
            for (int i = 0; i < 4; i++) {
                float4 v = va[i];
                __nv_bfloat16 h0 = __float2bfloat16(v.x), h1 = __float2bfloat16(v.y);
                __nv_bfloat16 h2 = __float2bfloat16(v.z), h3 = __float2bfloat16(v.w);
                dh[i * 2 + 0] = __nv_bfloat162(h0, h1);
                dh[i * 2 + 1] = __nv_bfloat162(h2, h3);
                dl[i * 2 + 0] = __nv_bfloat162(
                    __float2bfloat16(v.x - __bfloat162float(h0)),
                    __float2bfloat16(v.y - __bfloat162float(h1)));
                dl[i * 2 + 1] = __nv_bfloat162(
                    __float2bfloat16(v.z - __bfloat162float(h2)),
                    __float2bfloat16(v.w - __bfloat162float(h3)));
            }
        }

        // ---- prefetch next A chunk (overlaps with MMAs below) ----
        if (kc < 7) {
            const float4* nxt = a_src + (kk + 32) / 4;
#pragma unroll
            for (int i = 0; i < 4; i++)
                va[i] = a_valid ? nxt[i] : make_float4(0.f, 0.f, 0.f, 0.f);
        }

        CP_ASYNC_WAIT_ALL();
        __syncthreads();

        // ---- MMA: 2 k16-steps per chunk ----
#pragma unroll
        for (int ks = 0; ks < 2; ks++) {
            int k0 = ks * 16;
            uint32_t ah[2][4], al[2][4];
#pragma unroll
            for (int mt = 0; mt < 2; mt++) {
                uint32_t aoff = (uint32_t)(((mw * 32 + mt * 16 + lm_r) * STR + k0 + lm_c) * 2);
                LDMATRIX_X4(ah[mt][0], ah[mt][1], ah[mt][2], ah[mt][3], uAhi + aoff);
                LDMATRIX_X4(al[mt][0], al[mt][1], al[mt][2], al[mt][3], uAlo + aoff);
            }
#pragma unroll
            for (int g = 0; g < 4; g++) {       // n16 tiles within warp's n64
                uint32_t boff = (uint32_t)(((nw * 64 + g * 16 + lm_r) * STR + k0 + lm_c) * 2);
                uint32_t q0, q1, q2, q3;
                LDMATRIX_X4(q0, q1, q2, q3, uBhi + boff);
#pragma unroll
                for (int mt = 0; mt < 2; mt++) {
                    MMA16816(acc[mt][2 * g],     ah[mt][0], ah[mt][1], ah[mt][2], ah[mt][3], q0, q2);
                    MMA16816(acc[mt][2 * g + 1], ah[mt][0], ah[mt][1], ah[mt][2], ah[mt][3], q1, q3);
                    MMA16816(acc[mt][2 * g],     al[mt][0], al[mt][1], al[mt][2], al[mt][3], q0, q2);
                    MMA16816(acc[mt][2 * g + 1], al[mt][0], al[mt][1], al[mt][2], al[mt][3], q1, q3);
                }
                LDMATRIX_X4(q0, q1, q2, q3, uBlo + boff);
#pragma unroll
                for (int mt = 0; mt < 2; mt++) {
                    MMA16816(acc[mt][2 * g],     ah[mt][0], ah[mt][1], ah[mt][2], ah[mt][3], q0, q2);
                    MMA16816(acc[mt][2 * g + 1], ah[mt][0], ah[mt][1], ah[mt][2], ah[mt][3], q1, q3);
                }
            }
        }
    }

    // ---- epilogue: store g_ft + fused el/er (no atomics) ----
    __syncthreads();                    // all MMAs done; smem reusable
    float4* scr = (float4*)sAhi;        // 64 float4 scratch
    float p[2][4];
#pragma unroll
    for (int mt = 0; mt < 2; mt++) {
        int r1 = row0 + mw * 32 + mt * 16 + (lane >> 2);
        int r2 = r1 + 8;
        float pl1 = 0.f, pr1 = 0.f, pl2 = 0.f, pr2 = 0.f;
#pragma unroll
        for (int nt = 0; nt < 8; nt++) {
            int c = nw * 64 + nt * 8 + (lane & 3) * 2;
            float wl0 = attn_l[c], wl1 = attn_l[c + 1];
            float wr0 = attn_r[c], wr1 = attn_r[c + 1];
            pl1 += acc[mt][nt][0] * wl0 + acc[mt][nt][1] * wl1;
            pr1 += acc[mt][nt][0] * wr0 + acc[mt][nt][1] * wr1;
            pl2 += acc[mt][nt][2] * wl0 + acc[mt][nt][3] * wl1;
            pr2 += acc[mt][nt][2] * wr0 + acc[mt][nt][3] * wr1;
            if (r1 < Nn)
                *(float2*)(g_ft + (size_t)r1 * OUTF + c) = make_float2(acc[mt][nt][0], acc[mt][nt][1]);
            if (r2 < Nn)
                *(float2*)(g_ft + (size_t)r2 * OUTF + c) = make_float2(acc[mt][nt][2], acc[mt][nt][3]);
        }
#pragma unroll
        for (int o = 1; o <= 2; o <<= 1) {
            pl1 += __shfl_xor_sync(0xFFFFFFFFu, pl1, o);
            pr1 += __shfl_xor_sync(0xFFFFFFFFu, pr1, o);
            pl2 += __shfl_xor_sync(0xFFFFFFFFu, pl2, o);
            pr2 += __shfl_xor_sync(0xFFFFFFFFu, pr2, o);
        }
        p[mt][0] = pl1; p[mt][1] = pr1; p[mt][2] = pl2; p[mt][3] = pr2;
        if (nw == 0 && (lane & 3) == 0)
            scr[(mw * 2 + mt) * 8 + (lane >> 2)] = make_float4(pl1, pr1, pl2, pr2);
    }
    __syncthreads();
    if (nw == 1 && (lane & 3) == 0) {
#pragma unroll
        for (int mt = 0; mt < 2; mt++) {
            float4 q = scr[(mw * 2 + mt) * 8 + (lane >> 2)];
            int r1 = row0 + mw * 32 + mt * 16 + (lane >> 2);
            int r2 = r1 + 8;
            if (r1 < Nn) { g_el[r1] = q.x + p[mt][0]; g_er[r1] = q.y + p[mt][1]; }
            if (r2 < Nn) { g_el[r2] = q.z + p[mt][2]; g_er[r2] = q.w + p[mt][3]; }
        }
    }
}

// ---------------------------------------------------------------------------
// Scan phase A: warp-shuffle scan over degrees (2 barriers); zeroes g_deg.
// ---------------------------------------------------------------------------
__global__ __launch_bounds__(SCAN_T) void k_scan_a() {
    __shared__ int ws[8];
    int t = threadIdx.x;
    int lane = t & 31, wp = t >> 5;
    int i = blockIdx.x * SCAN_T + t;
    int d = (i < Nn) ? g_deg[i] : 0;
    if (i < Nn) g_deg[i] = 0;          // self-reset for next replay

    int v = d;                          // warp-inclusive scan
#pragma unroll
    for (int o = 1; o < 32; o <<= 1) {
        int n = __shfl_up_sync(0xFFFFFFFFu, v, o);
        if (lane >= o) v += n;
    }
    if (lane == 31) ws[wp] = v;
    __syncthreads();
    if (t < 8) {
        int s = ws[t];
#pragma unroll
        for (int o = 1; o < 8; o <<= 1) {
            int n = __shfl_up_sync(0xFFu, s, o);
            if (t >= o) s += n;
        }
        ws[t] = s;                      // inclusive warp-sum prefix
    }
    __syncthreads();
    int wpref = wp ? ws[wp - 1] : 0;
    if (i < Nn) g_off[i] = wpref + v - d;           // exclusive within block
    if (t == SCAN_T - 1) g_blk[blockIdx.x] = ws[7]; // block total
}

// ---------------------------------------------------------------------------
// Scan phase C (fused B): warp-shuffle reduce g_blk[0..b), add prefix.
// ---------------------------------------------------------------------------
__global__ __launch_bounds__(SCAN_T) void k_scan_c() {
    __shared__ int ws[8];
    __shared__ int spref;
    int t = threadIdx.x;
    int lane = t & 31, wp = t >> 5;
    int b = blockIdx.x;

    int x = (t < b && t < SCAN_BLOCKS) ? g_blk[t] : 0;
#pragma unroll
    for (int o = 16; o; o >>= 1) x += __shfl_xor_sync(0xFFFFFFFFu, x, o);
    if (lane == 0) ws[wp] = x;
    __syncthreads();
    if (t == 0) {
        int s = 0;
#pragma unroll
        for (int j = 0; j < 8; j++) s += ws[j];
        spref = s;
    }
    __syncthreads();

    int i = b * SCAN_T + t;
    if (i < Nn) g_off[i] += spref;
    if (i == 0) g_off[Nn] = Ee;
}

// ---------------------------------------------------------------------------
// Scatter: NO atomics — pos = off[dst] + precomputed rank. One float4 store.
// ---------------------------------------------------------------------------
__global__ void k_scatter(const float* __restrict__ w,
                          const int* __restrict__ src, const int* __restrict__ dst) {
    int i = blockIdx.x * blockDim.x + threadIdx.x;
    if (i >= Ee) return;
    int s = src[i], d = dst[i];
    float e = g_el[s] + g_er[d];
    e = e > 0.f ? e : NEG_SLOPE * e;
    float z  = expf(e);
    float zw = expf(w[i]);
    int pos = g_off[d] + g_pos[i];
    g_sz[pos] = make_float4(__int_as_float(s), z, zw, 0.f);
}

// ---------------------------------------------------------------------------
// CSR aggregation: one warp per dst node, no atomics. Pass 1 warp-reduces
// se/sw; pass 2 gathers ft[src] with 4-deep LDG pipelining (MLP=4).
// ---------------------------------------------------------------------------
__global__ __launch_bounds__(256) void k_agg_csr(const float* __restrict__ bias,
                                                 float* __restrict__ out) {
    int node = blockIdx.x * 8 + (threadIdx.x >> 5);
    int lane = threadIdx.x & 31;
    if (node >= Nn) return;
    int beg = g_off[node], end = g_off[node + 1];

    // pass 1: segment sums
    float se = 0.f, sw = 0.f;
    for (int i = beg + lane; i < end; i += 32) {
        float4 t = g_sz[i];
        se += t.y;
        sw += t.z;
    }
#pragma unroll
    for (int o = 16; o; o >>= 1) {
        se += __shfl_xor_sync(0xFFFFFFFFu, se, o);
        sw += __shfl_xor_sync(0xFFFFFFFFu, sw, o);
    }
    float inv_se = __fdividef(1.f - ALPHA, se);
    float inv_sw = __fdividef(ALPHA, sw);

    float4 acc = *(const float4*)(bias + lane * 4);
    const float* ftl = g_ft + lane * 4;

    for (int base = beg; base < end; base += 32) {
        int n = min(32, end - base);
        int s = 0;
        float a = 0.f;
        if (lane < n) {
            float4 t = g_sz[base + lane];
            s = __float_as_int(t.x);
            a = t.y * inv_se + t.z * inv_sw;
        }
        int j = 0;
        for (; j + 4 <= n; j += 4) {
            int   s0 = __shfl_sync(0xFFFFFFFFu, s, j);
            int   s1 = __shfl_sync(0xFFFFFFFFu, s, j + 1);
            int   s2 = __shfl_sync(0xFFFFFFFFu, s, j + 2);
            int   s3 = __shfl_sync(0xFFFFFFFFu, s, j + 3);
            float a0 = __shfl_sync(0xFFFFFFFFu, a, j);
            float a1 = __shfl_sync(0xFFFFFFFFu, a, j + 1);
            float a2 = __shfl_sync(0xFFFFFFFFu, a, j + 2);
            float a3 = __shfl_sync(0xFFFFFFFFu, a, j + 3);
            float4 v0 = *(const float4*)(ftl + (size_t)s0 * OUTF);
            float4 v1 = *(const float4*)(ftl + (size_t)s1 * OUTF);
            float4 v2 = *(const float4*)(ftl + (size_t)s2 * OUTF);
            float4 v3 = *(const float4*)(ftl + (size_t)s3 * OUTF);
            acc.x = fmaf(a0, v0.x, acc.x); acc.y = fmaf(a0, v0.y, acc.y);
            acc.z = fmaf(a0, v0.z, acc.z); acc.w = fmaf(a0, v0.w, acc.w);
            acc.x = fmaf(a1, v1.x, acc.x); acc.y = fmaf(a1, v1.y, acc.y);
            acc.z = fmaf(a1, v1.z, acc.z); acc.w = fmaf(a1, v1.w, acc.w);
            acc.x = fmaf(a2, v2.x, acc.x); acc.y = fmaf(a2, v2.y, acc.y);
            acc.z = fmaf(a2, v2.z, acc.z); acc.w = fmaf(a2, v2.w, acc.w);
            acc.x = fmaf(a3, v3.x, acc.x); acc.y = fmaf(a3, v3.y, acc.y);
            acc.z = fmaf(a3, v3.z, acc.z); acc.w = fmaf(a3, v3.w, acc.w);
        }
        for (; j < n; j++) {
            int   sj = __shfl_sync(0xFFFFFFFFu, s, j);
            float aj = __shfl_sync(0xFFFFFFFFu, a, j);
            float4 v = *(const float4*)(ftl + (size_t)sj * OUTF);
            acc.x = fmaf(aj, v.x, acc.x);
            acc.y = fmaf(aj, v.y, acc.y);
            acc.z = fmaf(aj, v.z, acc.z);
            acc.w = fmaf(aj, v.w, acc.w);
        }
    }
    *(float4*)(out + (size_t)node * OUTF + lane * 4) = acc;
}

extern "C" void kernel_launch(void* const* d_in, const int* in_sizes, int n_in,
                              void* d_out, int out_size) {
    const float* feat   = (const float*)d_in[0];
    const float* w      = (const float*)d_in[1];
    const float* fcw    = (const float*)d_in[2];
    const float* attn_l = (const float*)d_in[3];
    const float* attn_r = (const float*)d_in[4];
    const float* bias   = (const float*)d_in[5];
    const int*   src    = (const int*)d_in[6];
    const int*   dst    = (const int*)d_in[7];
    float* out = (float*)d_out;

    k_pre<<<BSPLIT_BLOCKS + DEG_BLOCKS, 256>>>(fcw, dst);
    k_scan_a<<<SCAN_BLOCKS, SCAN_T>>>();
    k_scan_c<<<SCAN_BLOCKS, SCAN_T>>>();
    k_gemm<<<(Nn + 127) / 128, 256>>>(feat, attn_l, attn_r);   // 4th: profiled
    k_scatter<<<(Ee + 255) / 256, 256>>>(w, src, dst);
    k_agg_csr<<<(Nn + 7) / 8, 256>>>(bias, out);
}